// round 15
// baseline (speedup 1.0000x reference)
#include <cuda_runtime.h>

// 2-layer LSTM (H=8, IN=2) + FC(8->1), T=1024, B=16384.
// E=4 elems/thread, 8 lanes/elem, 1024 single-warp blocks (one wave),
// within-thread layer pipeline (step i computes h0(i) and h1(i-1)).
// GATE-PAIRED f32x2 matvecs: accumulators hold (z_i,z_f)/(z_g,z_o) so
// horizontal adds disappear; h is stored DUPLICATED in smem ((h,h) per
// STS.64) and read back as LDS.128 pairs. Activation algebra is f32x2-
// packed across element pairs. tanh.approx activations, sigmoid gates
// via half-prescaled weights.

using u64 = unsigned long long;

__device__ __forceinline__ u64 pack2(float lo, float hi) {
    u64 r; asm("mov.b64 %0, {%1, %2};" : "=l"(r) : "f"(lo), "f"(hi)); return r;
}
__device__ __forceinline__ float2 unpack2(u64 v) {
    float2 f; asm("mov.b64 {%0, %1}, %2;" : "=f"(f.x), "=f"(f.y) : "l"(v)); return f;
}
__device__ __forceinline__ u64 ffma2(u64 a, u64 b, u64 c) {
    u64 d; asm("fma.rn.f32x2 %0, %1, %2, %3;" : "=l"(d) : "l"(a), "l"(b), "l"(c)); return d;
}
__device__ __forceinline__ u64 fmul2(u64 a, u64 b) {
    u64 d; asm("mul.rn.f32x2 %0, %1, %2;" : "=l"(d) : "l"(a), "l"(b)); return d;
}
__device__ __forceinline__ float tanh_a(float x) {
    float y; asm("tanh.approx.f32 %0, %1;" : "=f"(y) : "f"(x)); return y;
}

// Activations for one layer, two elements at once.
// zA* = (z_i, z_f) prescaled by 0.5; zB* = (z_g, z_o) with o prescaled.
// c01 = packed (c_e0, c_e1). Outputs scalar h for each element.
__device__ __forceinline__ void act_pair(u64 zA0, u64 zA1, u64 zB0, u64 zB1,
                                         u64& c01, float& h_0, float& h_1)
{
    const u64 HALF2 = 0x3f0000003f000000ull;   // (0.5f, 0.5f)
    float2 a0 = unpack2(zA0);
    float2 a1 = unpack2(zA1);
    float2 b0 = unpack2(zB0);
    float2 b1 = unpack2(zB1);
    u64 I = pack2(tanh_a(a0.x), tanh_a(a1.x));
    u64 F = pack2(tanh_a(a0.y), tanh_a(a1.y));
    u64 G = pack2(tanh_a(b0.x), tanh_a(b1.x));
    u64 O = pack2(tanh_a(b0.y), tanh_a(b1.y));
    u64 i01 = ffma2(I, HALF2, HALF2);
    u64 f01 = ffma2(F, HALF2, HALF2);
    u64 o01 = ffma2(O, HALF2, HALF2);
    c01 = ffma2(f01, c01, fmul2(i01, G));
    float2 cu = unpack2(c01);
    u64 tc = pack2(tanh_a(cu.x), tanh_a(cu.y));
    float2 hu = unpack2(fmul2(o01, tc));
    h_0 = hu.x; h_1 = hu.y;
}

__global__ void __launch_bounds__(32)
lstm2_fc_kernel(const float* __restrict__ x,
                const float* __restrict__ w_ih0, const float* __restrict__ w_hh0,
                const float* __restrict__ b_ih0, const float* __restrict__ b_hh0,
                const float* __restrict__ w_ih1, const float* __restrict__ w_hh1,
                const float* __restrict__ b_ih1, const float* __restrict__ b_hh1,
                const float* __restrict__ fc_w, const float* __restrict__ fc_b,
                float* __restrict__ out, int T, int B)
{
    // Duplicated h state: [slot][elem p][quad ql][k][dup2]. One STS.64 per
    // (elem,layer) write; LDS.128 gives two duplicated-pair u64s per read.
    __shared__ alignas(16) float h0d[2][4][4][8][2];
    __shared__ alignas(16) float h1d[2][4][4][8][2];

    int lane  = threadIdx.x;
    int ql    = lane >> 3;
    int j     = lane & 7;
    int q     = blockIdx.x * 4 + ql;
    int quadB = B >> 2;
    bool valid = (q < quadB);
    if (!valid) q = quadB - 1;

    // ---- Gate-paired weights. Rows: i=j, f=8+j, g=16+j, o=24+j.
    //      Chain A = (i,f) both scaled 0.5; chain B = (g,o), o scaled 0.5. ----
    int iR = j, fR = 8 + j, gR = 16 + j, oR = 24 + j;
    u64 wax[2], wbx[2], wah[8], wbh[8];
    u64 wia[8], wib[8], wha[8], whb[8];
#pragma unroll
    for (int k = 0; k < 2; k++) {
        wax[k] = pack2(0.5f * __ldg(&w_ih0[iR * 2 + k]), 0.5f * __ldg(&w_ih0[fR * 2 + k]));
        wbx[k] = pack2(       __ldg(&w_ih0[gR * 2 + k]), 0.5f * __ldg(&w_ih0[oR * 2 + k]));
    }
#pragma unroll
    for (int k = 0; k < 8; k++) {
        wah[k] = pack2(0.5f * __ldg(&w_hh0[iR * 8 + k]), 0.5f * __ldg(&w_hh0[fR * 8 + k]));
        wbh[k] = pack2(       __ldg(&w_hh0[gR * 8 + k]), 0.5f * __ldg(&w_hh0[oR * 8 + k]));
        wia[k] = pack2(0.5f * __ldg(&w_ih1[iR * 8 + k]), 0.5f * __ldg(&w_ih1[fR * 8 + k]));
        wib[k] = pack2(       __ldg(&w_ih1[gR * 8 + k]), 0.5f * __ldg(&w_ih1[oR * 8 + k]));
        wha[k] = pack2(0.5f * __ldg(&w_hh1[iR * 8 + k]), 0.5f * __ldg(&w_hh1[fR * 8 + k]));
        whb[k] = pack2(       __ldg(&w_hh1[gR * 8 + k]), 0.5f * __ldg(&w_hh1[oR * 8 + k]));
    }
    u64 bA0 = pack2(0.5f * (__ldg(&b_ih0[iR]) + __ldg(&b_hh0[iR])),
                    0.5f * (__ldg(&b_ih0[fR]) + __ldg(&b_hh0[fR])));
    u64 bB0 = pack2(       (__ldg(&b_ih0[gR]) + __ldg(&b_hh0[gR])),
                    0.5f * (__ldg(&b_ih0[oR]) + __ldg(&b_hh0[oR])));
    u64 bA1 = pack2(0.5f * (__ldg(&b_ih1[iR]) + __ldg(&b_hh1[iR])),
                    0.5f * (__ldg(&b_ih1[fR]) + __ldg(&b_hh1[fR])));
    u64 bB1 = pack2(       (__ldg(&b_ih1[gR]) + __ldg(&b_hh1[gR])),
                    0.5f * (__ldg(&b_ih1[oR]) + __ldg(&b_hh1[oR])));

    // Cell state packed across element pairs: c*p[pp] = (c[2pp], c[2pp+1]).
    u64 c0p[2] = { 0ull, 0ull }, c1p[2] = { 0ull, 0ull };

    int strideT = B >> 1;
    const ulonglong2* xp = (const ulonglong2*)x + 2 * q;
    ulonglong2 xa = __ldg(xp);
    ulonglong2 xb = __ldg(xp + 1);

    // ================= Prologue: h0(0) = L0(x(0), 0); h1d[0] = 0 =================
    {
#pragma unroll
        for (int p = 0; p < 4; p++)
            *(u64*)&h1d[0][p][ql][j][0] = 0ull;
        u64 xe[4] = { xa.x, xa.y, xb.x, xb.y };
#pragma unroll
        for (int pp = 0; pp < 2; pp++) {
            u64 zA[2], zB[2];
#pragma unroll
            for (int e = 0; e < 2; e++) {
                float2 xu = unpack2(xe[2 * pp + e]);
                u64 xd0 = pack2(xu.x, xu.x), xd1 = pack2(xu.y, xu.y);
                u64 a = ffma2(wax[0], xd0, bA0); a = ffma2(wax[1], xd1, a);
                u64 b = ffma2(wbx[0], xd0, bB0); b = ffma2(wbx[1], xd1, b);
                zA[e] = a; zB[e] = b;
            }
            float h_0, h_1;
            act_pair(zA[0], zA[1], zB[0], zB[1], c0p[pp], h_0, h_1);
            *(u64*)&h0d[0][2 * pp    ][ql][j][0] = pack2(h_0, h_0);
            *(u64*)&h0d[0][2 * pp + 1][ql][j][0] = pack2(h_1, h_1);
        }
        __syncwarp();
        if (T > 1) { xp += strideT; xa = __ldg(xp); xb = __ldg(xp + 1); }
    }

    // ============ Main loop: i = 1..T-1 computes h0(i) & h1(i-1) ============
#pragma unroll 1
    for (int i = 1; i < T; i++) {
        const ulonglong2* xn = xp + ((i + 1 < T) ? strideT : 0);
        ulonglong2 na = __ldg(xn);
        ulonglong2 nb = __ldg(xn + 1);
        int s = i & 1, s1 = s ^ 1;
        u64 xe[4] = { xa.x, xa.y, xb.x, xb.y };

#pragma unroll
        for (int pp = 0; pp < 2; pp++) {
            u64 zA0[2], zB0[2], zA1[2], zB1[2];
#pragma unroll
            for (int e = 0; e < 2; e++) {
                int p = 2 * pp + e;
                const ulonglong2* r0 = (const ulonglong2*)&h0d[s1][p][ql][0][0];
                ulonglong2 v0 = r0[0], v1 = r0[1], v2 = r0[2], v3 = r0[3];
                u64 hd0[8] = { v0.x, v0.y, v1.x, v1.y, v2.x, v2.y, v3.x, v3.y };
                const ulonglong2* r1 = (const ulonglong2*)&h1d[s1][p][ql][0][0];
                ulonglong2 w0 = r1[0], w1 = r1[1], w2 = r1[2], w3 = r1[3];
                u64 hd1[8] = { w0.x, w0.y, w1.x, w1.y, w2.x, w2.y, w3.x, w3.y };

                float2 xu = unpack2(xe[p]);
                u64 xd0 = pack2(xu.x, xu.x), xd1 = pack2(xu.y, xu.y);

                u64 a0 = ffma2(wax[0], xd0, bA0); a0 = ffma2(wax[1], xd1, a0);
                u64 b0 = ffma2(wbx[0], xd0, bB0); b0 = ffma2(wbx[1], xd1, b0);
                u64 a1 = bA1, b1 = bB1;
#pragma unroll
                for (int k = 0; k < 8; k++) {
                    a0 = ffma2(wah[k], hd0[k], a0);
                    b0 = ffma2(wbh[k], hd0[k], b0);
                    a1 = ffma2(wia[k], hd0[k], a1);
                    b1 = ffma2(wib[k], hd0[k], b1);
                }
#pragma unroll
                for (int k = 0; k < 8; k++) {
                    a1 = ffma2(wha[k], hd1[k], a1);
                    b1 = ffma2(whb[k], hd1[k], b1);
                }
                zA0[e] = a0; zB0[e] = b0; zA1[e] = a1; zB1[e] = b1;
            }
            float p0h0, p1h0, p0h1, p1h1;
            act_pair(zA0[0], zA0[1], zB0[0], zB0[1], c0p[pp], p0h0, p1h0);
            act_pair(zA1[0], zA1[1], zB1[0], zB1[1], c1p[pp], p0h1, p1h1);
            *(u64*)&h0d[s][2 * pp    ][ql][j][0] = pack2(p0h0, p0h0);
            *(u64*)&h0d[s][2 * pp + 1][ql][j][0] = pack2(p1h0, p1h0);
            *(u64*)&h1d[s][2 * pp    ][ql][j][0] = pack2(p0h1, p0h1);
            *(u64*)&h1d[s][2 * pp + 1][ql][j][0] = pack2(p1h1, p1h1);
        }
        __syncwarp();
        xa = na; xb = nb; xp = xn;
    }

    // ============ Epilogue: h1(T-1) = L1(h0(T-1), h1(T-2)) + FC ============
    {
        int sl = (T - 1) & 1;
        float h1f[4];
#pragma unroll
        for (int pp = 0; pp < 2; pp++) {
            u64 zA1[2], zB1[2];
#pragma unroll
            for (int e = 0; e < 2; e++) {
                int p = 2 * pp + e;
                const ulonglong2* r0 = (const ulonglong2*)&h0d[sl][p][ql][0][0];
                ulonglong2 v0 = r0[0], v1 = r0[1], v2 = r0[2], v3 = r0[3];
                u64 hd0[8] = { v0.x, v0.y, v1.x, v1.y, v2.x, v2.y, v3.x, v3.y };
                const ulonglong2* r1 = (const ulonglong2*)&h1d[sl][p][ql][0][0];
                ulonglong2 w0 = r1[0], w1 = r1[1], w2 = r1[2], w3 = r1[3];
                u64 hd1[8] = { w0.x, w0.y, w1.x, w1.y, w2.x, w2.y, w3.x, w3.y };

                u64 a1 = bA1, b1 = bB1;
#pragma unroll
                for (int k = 0; k < 8; k++) {
                    a1 = ffma2(wia[k], hd0[k], a1);
                    b1 = ffma2(wib[k], hd0[k], b1);
                }
#pragma unroll
                for (int k = 0; k < 8; k++) {
                    a1 = ffma2(wha[k], hd1[k], a1);
                    b1 = ffma2(whb[k], hd1[k], b1);
                }
                zA1[e] = a1; zB1[e] = b1;
            }
            float ha, hb;
            act_pair(zA1[0], zA1[1], zB1[0], zB1[1], c1p[pp], ha, hb);
            h1f[2 * pp] = ha; h1f[2 * pp + 1] = hb;
        }

        // FC: out[b] = sum_j fc_w[j]*h1[j] + fc_b via width-8 shfl reduction.
        float fwj = __ldg(&fc_w[j]);
        float fb  = __ldg(&fc_b[0]);
        float4 o;
        float* op = &o.x;
#pragma unroll
        for (int p = 0; p < 4; p++) {
            float v = fwj * h1f[p];
#pragma unroll
            for (int d = 4; d >= 1; d >>= 1)
                v += __shfl_down_sync(0xffffffffu, v, d, 8);
            op[p] = v + fb;
        }
        if (valid && j == 0)
            *(float4*)&out[4 * q] = o;
    }
}

extern "C" void kernel_launch(void* const* d_in, const int* in_sizes, int n_in,
                              void* d_out, int out_size)
{
    const float* x      = (const float*)d_in[0];
    const float* w_ih0  = (const float*)d_in[1];
    const float* w_hh0  = (const float*)d_in[2];
    const float* b_ih0  = (const float*)d_in[3];
    const float* b_hh0  = (const float*)d_in[4];
    const float* w_ih1  = (const float*)d_in[5];
    const float* w_hh1  = (const float*)d_in[6];
    const float* b_ih1  = (const float*)d_in[7];
    const float* b_hh1  = (const float*)d_in[8];
    const float* fc_w   = (const float*)d_in[9];
    const float* fc_b   = (const float*)d_in[10];
    float* out = (float*)d_out;

    int B = out_size;                 // [B, 1]
    int T = in_sizes[0] / (2 * B);    // x: [T, B, 2]

    int blocks = (B + 15) / 16;       // 16 elements per warp-block
    lstm2_fc_kernel<<<blocks, 32>>>(x, w_ih0, w_hh0, b_ih0, b_hh0,
                                    w_ih1, w_hh1, b_ih1, b_hh1,
                                    fc_w, fc_b, out, T, B);
}

// round 16
// speedup vs baseline: 1.0017x; 1.0017x over previous
#include <cuda_runtime.h>

// 2-layer LSTM (H=8, IN=2) + FC(8->1), T=1024, B=16384.
// E=4 elems/thread, 8 lanes/elem, 1024 single-warp blocks (one wave),
// within-thread layer pipeline (step i computes h0(i) and h1(i-1)).
// GATE-PAIRED f32x2 matvecs: accumulators hold (z_i,z_f)/(z_g,z_o) so
// horizontal adds disappear; h is stored DUPLICATED in smem ((h,h) per
// STS.64) and read back as LDS.128 pairs. Activation algebra is f32x2-
// packed across element pairs. tanh.approx activations, sigmoid gates
// via half-prescaled weights.

using u64 = unsigned long long;

__device__ __forceinline__ u64 pack2(float lo, float hi) {
    u64 r; asm("mov.b64 %0, {%1, %2};" : "=l"(r) : "f"(lo), "f"(hi)); return r;
}
__device__ __forceinline__ float2 unpack2(u64 v) {
    float2 f; asm("mov.b64 {%0, %1}, %2;" : "=f"(f.x), "=f"(f.y) : "l"(v)); return f;
}
__device__ __forceinline__ u64 ffma2(u64 a, u64 b, u64 c) {
    u64 d; asm("fma.rn.f32x2 %0, %1, %2, %3;" : "=l"(d) : "l"(a), "l"(b), "l"(c)); return d;
}
__device__ __forceinline__ u64 fmul2(u64 a, u64 b) {
    u64 d; asm("mul.rn.f32x2 %0, %1, %2;" : "=l"(d) : "l"(a), "l"(b)); return d;
}
__device__ __forceinline__ float tanh_a(float x) {
    float y; asm("tanh.approx.f32 %0, %1;" : "=f"(y) : "f"(x)); return y;
}

// Activations for one layer, two elements at once.
// zA* = (z_i, z_f) prescaled by 0.5; zB* = (z_g, z_o) with o prescaled.
// c01 = packed (c_e0, c_e1). Outputs scalar h for each element.
__device__ __forceinline__ void act_pair(u64 zA0, u64 zA1, u64 zB0, u64 zB1,
                                         u64& c01, float& h_0, float& h_1)
{
    const u64 HALF2 = 0x3f0000003f000000ull;   // (0.5f, 0.5f)
    float2 a0 = unpack2(zA0);
    float2 a1 = unpack2(zA1);
    float2 b0 = unpack2(zB0);
    float2 b1 = unpack2(zB1);
    u64 I = pack2(tanh_a(a0.x), tanh_a(a1.x));
    u64 F = pack2(tanh_a(a0.y), tanh_a(a1.y));
    u64 G = pack2(tanh_a(b0.x), tanh_a(b1.x));
    u64 O = pack2(tanh_a(b0.y), tanh_a(b1.y));
    u64 i01 = ffma2(I, HALF2, HALF2);
    u64 f01 = ffma2(F, HALF2, HALF2);
    u64 o01 = ffma2(O, HALF2, HALF2);
    c01 = ffma2(f01, c01, fmul2(i01, G));
    float2 cu = unpack2(c01);
    u64 tc = pack2(tanh_a(cu.x), tanh_a(cu.y));
    float2 hu = unpack2(fmul2(o01, tc));
    h_0 = hu.x; h_1 = hu.y;
}

__global__ void __launch_bounds__(32)
lstm2_fc_kernel(const float* __restrict__ x,
                const float* __restrict__ w_ih0, const float* __restrict__ w_hh0,
                const float* __restrict__ b_ih0, const float* __restrict__ b_hh0,
                const float* __restrict__ w_ih1, const float* __restrict__ w_hh1,
                const float* __restrict__ b_ih1, const float* __restrict__ b_hh1,
                const float* __restrict__ fc_w, const float* __restrict__ fc_b,
                float* __restrict__ out, int T, int B)
{
    // Duplicated h state: [slot][elem p][quad ql][k][dup2]. One STS.64 per
    // (elem,layer) write; LDS.128 gives two duplicated-pair u64s per read.
    __shared__ alignas(16) float h0d[2][4][4][8][2];
    __shared__ alignas(16) float h1d[2][4][4][8][2];

    int lane  = threadIdx.x;
    int ql    = lane >> 3;
    int j     = lane & 7;
    int q     = blockIdx.x * 4 + ql;
    int quadB = B >> 2;
    bool valid = (q < quadB);
    if (!valid) q = quadB - 1;

    // ---- Gate-paired weights. Rows: i=j, f=8+j, g=16+j, o=24+j.
    //      Chain A = (i,f) both scaled 0.5; chain B = (g,o), o scaled 0.5. ----
    int iR = j, fR = 8 + j, gR = 16 + j, oR = 24 + j;
    u64 wax[2], wbx[2], wah[8], wbh[8];
    u64 wia[8], wib[8], wha[8], whb[8];
#pragma unroll
    for (int k = 0; k < 2; k++) {
        wax[k] = pack2(0.5f * __ldg(&w_ih0[iR * 2 + k]), 0.5f * __ldg(&w_ih0[fR * 2 + k]));
        wbx[k] = pack2(       __ldg(&w_ih0[gR * 2 + k]), 0.5f * __ldg(&w_ih0[oR * 2 + k]));
    }
#pragma unroll
    for (int k = 0; k < 8; k++) {
        wah[k] = pack2(0.5f * __ldg(&w_hh0[iR * 8 + k]), 0.5f * __ldg(&w_hh0[fR * 8 + k]));
        wbh[k] = pack2(       __ldg(&w_hh0[gR * 8 + k]), 0.5f * __ldg(&w_hh0[oR * 8 + k]));
        wia[k] = pack2(0.5f * __ldg(&w_ih1[iR * 8 + k]), 0.5f * __ldg(&w_ih1[fR * 8 + k]));
        wib[k] = pack2(       __ldg(&w_ih1[gR * 8 + k]), 0.5f * __ldg(&w_ih1[oR * 8 + k]));
        wha[k] = pack2(0.5f * __ldg(&w_hh1[iR * 8 + k]), 0.5f * __ldg(&w_hh1[fR * 8 + k]));
        whb[k] = pack2(       __ldg(&w_hh1[gR * 8 + k]), 0.5f * __ldg(&w_hh1[oR * 8 + k]));
    }
    u64 bA0 = pack2(0.5f * (__ldg(&b_ih0[iR]) + __ldg(&b_hh0[iR])),
                    0.5f * (__ldg(&b_ih0[fR]) + __ldg(&b_hh0[fR])));
    u64 bB0 = pack2(       (__ldg(&b_ih0[gR]) + __ldg(&b_hh0[gR])),
                    0.5f * (__ldg(&b_ih0[oR]) + __ldg(&b_hh0[oR])));
    u64 bA1 = pack2(0.5f * (__ldg(&b_ih1[iR]) + __ldg(&b_hh1[iR])),
                    0.5f * (__ldg(&b_ih1[fR]) + __ldg(&b_hh1[fR])));
    u64 bB1 = pack2(       (__ldg(&b_ih1[gR]) + __ldg(&b_hh1[gR])),
                    0.5f * (__ldg(&b_ih1[oR]) + __ldg(&b_hh1[oR])));

    // Cell state packed across element pairs: c*p[pp] = (c[2pp], c[2pp+1]).
    u64 c0p[2] = { 0ull, 0ull }, c1p[2] = { 0ull, 0ull };

    int strideT = B >> 1;
    const ulonglong2* xp = (const ulonglong2*)x + 2 * q;
    ulonglong2 xa = __ldg(xp);
    ulonglong2 xb = __ldg(xp + 1);

    // ================= Prologue: h0(0) = L0(x(0), 0); h1d[0] = 0 =================
    {
#pragma unroll
        for (int p = 0; p < 4; p++)
            *(u64*)&h1d[0][p][ql][j][0] = 0ull;
        u64 xe[4] = { xa.x, xa.y, xb.x, xb.y };
#pragma unroll
        for (int pp = 0; pp < 2; pp++) {
            u64 zA[2], zB[2];
#pragma unroll
            for (int e = 0; e < 2; e++) {
                float2 xu = unpack2(xe[2 * pp + e]);
                u64 xd0 = pack2(xu.x, xu.x), xd1 = pack2(xu.y, xu.y);
                u64 a = ffma2(wax[0], xd0, bA0); a = ffma2(wax[1], xd1, a);
                u64 b = ffma2(wbx[0], xd0, bB0); b = ffma2(wbx[1], xd1, b);
                zA[e] = a; zB[e] = b;
            }
            float h_0, h_1;
            act_pair(zA[0], zA[1], zB[0], zB[1], c0p[pp], h_0, h_1);
            *(u64*)&h0d[0][2 * pp    ][ql][j][0] = pack2(h_0, h_0);
            *(u64*)&h0d[0][2 * pp + 1][ql][j][0] = pack2(h_1, h_1);
        }
        __syncwarp();
        if (T > 1) { xp += strideT; xa = __ldg(xp); xb = __ldg(xp + 1); }
    }

    // ============ Main loop: i = 1..T-1 computes h0(i) & h1(i-1) ============
#pragma unroll 1
    for (int i = 1; i < T; i++) {
        const ulonglong2* xn = xp + ((i + 1 < T) ? strideT : 0);
        ulonglong2 na = __ldg(xn);
        ulonglong2 nb = __ldg(xn + 1);
        int s = i & 1, s1 = s ^ 1;
        u64 xe[4] = { xa.x, xa.y, xb.x, xb.y };

#pragma unroll
        for (int pp = 0; pp < 2; pp++) {
            u64 zA0[2], zB0[2], zA1[2], zB1[2];
#pragma unroll
            for (int e = 0; e < 2; e++) {
                int p = 2 * pp + e;
                const ulonglong2* r0 = (const ulonglong2*)&h0d[s1][p][ql][0][0];
                ulonglong2 v0 = r0[0], v1 = r0[1], v2 = r0[2], v3 = r0[3];
                u64 hd0[8] = { v0.x, v0.y, v1.x, v1.y, v2.x, v2.y, v3.x, v3.y };
                const ulonglong2* r1 = (const ulonglong2*)&h1d[s1][p][ql][0][0];
                ulonglong2 w0 = r1[0], w1 = r1[1], w2 = r1[2], w3 = r1[3];
                u64 hd1[8] = { w0.x, w0.y, w1.x, w1.y, w2.x, w2.y, w3.x, w3.y };

                float2 xu = unpack2(xe[p]);
                u64 xd0 = pack2(xu.x, xu.x), xd1 = pack2(xu.y, xu.y);

                u64 a0 = ffma2(wax[0], xd0, bA0); a0 = ffma2(wax[1], xd1, a0);
                u64 b0 = ffma2(wbx[0], xd0, bB0); b0 = ffma2(wbx[1], xd1, b0);
                u64 a1 = bA1, b1 = bB1;
#pragma unroll
                for (int k = 0; k < 8; k++) {
                    a0 = ffma2(wah[k], hd0[k], a0);
                    b0 = ffma2(wbh[k], hd0[k], b0);
                    a1 = ffma2(wia[k], hd0[k], a1);
                    b1 = ffma2(wib[k], hd0[k], b1);
                }
#pragma unroll
                for (int k = 0; k < 8; k++) {
                    a1 = ffma2(wha[k], hd1[k], a1);
                    b1 = ffma2(whb[k], hd1[k], b1);
                }
                zA0[e] = a0; zB0[e] = b0; zA1[e] = a1; zB1[e] = b1;
            }
            float p0h0, p1h0, p0h1, p1h1;
            act_pair(zA0[0], zA0[1], zB0[0], zB0[1], c0p[pp], p0h0, p1h0);
            act_pair(zA1[0], zA1[1], zB1[0], zB1[1], c1p[pp], p0h1, p1h1);
            *(u64*)&h0d[s][2 * pp    ][ql][j][0] = pack2(p0h0, p0h0);
            *(u64*)&h0d[s][2 * pp + 1][ql][j][0] = pack2(p1h0, p1h0);
            *(u64*)&h1d[s][2 * pp    ][ql][j][0] = pack2(p0h1, p0h1);
            *(u64*)&h1d[s][2 * pp + 1][ql][j][0] = pack2(p1h1, p1h1);
        }
        __syncwarp();
        xa = na; xb = nb; xp = xn;
    }

    // ============ Epilogue: h1(T-1) = L1(h0(T-1), h1(T-2)) + FC ============
    {
        int sl = (T - 1) & 1;
        float h1f[4];
#pragma unroll
        for (int pp = 0; pp < 2; pp++) {
            u64 zA1[2], zB1[2];
#pragma unroll
            for (int e = 0; e < 2; e++) {
                int p = 2 * pp + e;
                const ulonglong2* r0 = (const ulonglong2*)&h0d[sl][p][ql][0][0];
                ulonglong2 v0 = r0[0], v1 = r0[1], v2 = r0[2], v3 = r0[3];
                u64 hd0[8] = { v0.x, v0.y, v1.x, v1.y, v2.x, v2.y, v3.x, v3.y };
                const ulonglong2* r1 = (const ulonglong2*)&h1d[sl][p][ql][0][0];
                ulonglong2 w0 = r1[0], w1 = r1[1], w2 = r1[2], w3 = r1[3];
                u64 hd1[8] = { w0.x, w0.y, w1.x, w1.y, w2.x, w2.y, w3.x, w3.y };

                u64 a1 = bA1, b1 = bB1;
#pragma unroll
                for (int k = 0; k < 8; k++) {
                    a1 = ffma2(wia[k], hd0[k], a1);
                    b1 = ffma2(wib[k], hd0[k], b1);
                }
#pragma unroll
                for (int k = 0; k < 8; k++) {
                    a1 = ffma2(wha[k], hd1[k], a1);
                    b1 = ffma2(whb[k], hd1[k], b1);
                }
                zA1[e] = a1; zB1[e] = b1;
            }
            float ha, hb;
            act_pair(zA1[0], zA1[1], zB1[0], zB1[1], c1p[pp], ha, hb);
            h1f[2 * pp] = ha; h1f[2 * pp + 1] = hb;
        }

        // FC: out[b] = sum_j fc_w[j]*h1[j] + fc_b via width-8 shfl reduction.
        float fwj = __ldg(&fc_w[j]);
        float fb  = __ldg(&fc_b[0]);
        float4 o;
        float* op = &o.x;
#pragma unroll
        for (int p = 0; p < 4; p++) {
            float v = fwj * h1f[p];
#pragma unroll
            for (int d = 4; d >= 1; d >>= 1)
                v += __shfl_down_sync(0xffffffffu, v, d, 8);
            op[p] = v + fb;
        }
        if (valid && j == 0)
            *(float4*)&out[4 * q] = o;
    }
}

extern "C" void kernel_launch(void* const* d_in, const int* in_sizes, int n_in,
                              void* d_out, int out_size)
{
    const float* x      = (const float*)d_in[0];
    const float* w_ih0  = (const float*)d_in[1];
    const float* w_hh0  = (const float*)d_in[2];
    const float* b_ih0  = (const float*)d_in[3];
    const float* b_hh0  = (const float*)d_in[4];
    const float* w_ih1  = (const float*)d_in[5];
    const float* w_hh1  = (const float*)d_in[6];
    const float* b_ih1  = (const float*)d_in[7];
    const float* b_hh1  = (const float*)d_in[8];
    const float* fc_w   = (const float*)d_in[9];
    const float* fc_b   = (const float*)d_in[10];
    float* out = (float*)d_out;

    int B = out_size;                 // [B, 1]
    int T = in_sizes[0] / (2 * B);    // x: [T, B, 2]

    int blocks = (B + 15) / 16;       // 16 elements per warp-block
    lstm2_fc_kernel<<<blocks, 32>>>(x, w_ih0, w_hh0, b_ih0, b_hh0,
                                    w_ih1, w_hh1, b_ih1, b_hh1,
                                    fc_w, fc_b, out, T, B);
}

// round 17
// speedup vs baseline: 1.0017x; 1.0001x over previous
#include <cuda_runtime.h>

// 2-layer LSTM (H=8, IN=2) + FC(8->1), T=1024, B=16384.
// E=4 elems/thread, 8 lanes/elem, 1024 single-warp blocks (one wave),
// within-thread layer pipeline (step i computes h0(i) and h1(i-1)).
// GATE-PAIRED f32x2 matvecs: accumulators hold (z_i,z_f)/(z_g,z_o) so
// horizontal adds disappear; h is stored DUPLICATED in smem ((h,h) per
// STS.64) and read back as LDS.128 pairs. Activation algebra is f32x2-
// packed across element pairs. tanh.approx activations, sigmoid gates
// via half-prescaled weights.

using u64 = unsigned long long;

__device__ __forceinline__ u64 pack2(float lo, float hi) {
    u64 r; asm("mov.b64 %0, {%1, %2};" : "=l"(r) : "f"(lo), "f"(hi)); return r;
}
__device__ __forceinline__ float2 unpack2(u64 v) {
    float2 f; asm("mov.b64 {%0, %1}, %2;" : "=f"(f.x), "=f"(f.y) : "l"(v)); return f;
}
__device__ __forceinline__ u64 ffma2(u64 a, u64 b, u64 c) {
    u64 d; asm("fma.rn.f32x2 %0, %1, %2, %3;" : "=l"(d) : "l"(a), "l"(b), "l"(c)); return d;
}
__device__ __forceinline__ u64 fmul2(u64 a, u64 b) {
    u64 d; asm("mul.rn.f32x2 %0, %1, %2;" : "=l"(d) : "l"(a), "l"(b)); return d;
}
__device__ __forceinline__ float tanh_a(float x) {
    float y; asm("tanh.approx.f32 %0, %1;" : "=f"(y) : "f"(x)); return y;
}

// Activations for one layer, two elements at once.
// zA* = (z_i, z_f) prescaled by 0.5; zB* = (z_g, z_o) with o prescaled.
// c01 = packed (c_e0, c_e1). Outputs scalar h for each element.
__device__ __forceinline__ void act_pair(u64 zA0, u64 zA1, u64 zB0, u64 zB1,
                                         u64& c01, float& h_0, float& h_1)
{
    const u64 HALF2 = 0x3f0000003f000000ull;   // (0.5f, 0.5f)
    float2 a0 = unpack2(zA0);
    float2 a1 = unpack2(zA1);
    float2 b0 = unpack2(zB0);
    float2 b1 = unpack2(zB1);
    u64 I = pack2(tanh_a(a0.x), tanh_a(a1.x));
    u64 F = pack2(tanh_a(a0.y), tanh_a(a1.y));
    u64 G = pack2(tanh_a(b0.x), tanh_a(b1.x));
    u64 O = pack2(tanh_a(b0.y), tanh_a(b1.y));
    u64 i01 = ffma2(I, HALF2, HALF2);
    u64 f01 = ffma2(F, HALF2, HALF2);
    u64 o01 = ffma2(O, HALF2, HALF2);
    c01 = ffma2(f01, c01, fmul2(i01, G));
    float2 cu = unpack2(c01);
    u64 tc = pack2(tanh_a(cu.x), tanh_a(cu.y));
    float2 hu = unpack2(fmul2(o01, tc));
    h_0 = hu.x; h_1 = hu.y;
}

__global__ void __launch_bounds__(32)
lstm2_fc_kernel(const float* __restrict__ x,
                const float* __restrict__ w_ih0, const float* __restrict__ w_hh0,
                const float* __restrict__ b_ih0, const float* __restrict__ b_hh0,
                const float* __restrict__ w_ih1, const float* __restrict__ w_hh1,
                const float* __restrict__ b_ih1, const float* __restrict__ b_hh1,
                const float* __restrict__ fc_w, const float* __restrict__ fc_b,
                float* __restrict__ out, int T, int B)
{
    // Duplicated h state: [slot][elem p][quad ql][k][dup2]. One STS.64 per
    // (elem,layer) write; LDS.128 gives two duplicated-pair u64s per read.
    __shared__ alignas(16) float h0d[2][4][4][8][2];
    __shared__ alignas(16) float h1d[2][4][4][8][2];

    int lane  = threadIdx.x;
    int ql    = lane >> 3;
    int j     = lane & 7;
    int q     = blockIdx.x * 4 + ql;
    int quadB = B >> 2;
    bool valid = (q < quadB);
    if (!valid) q = quadB - 1;

    // ---- Gate-paired weights. Rows: i=j, f=8+j, g=16+j, o=24+j.
    //      Chain A = (i,f) both scaled 0.5; chain B = (g,o), o scaled 0.5. ----
    int iR = j, fR = 8 + j, gR = 16 + j, oR = 24 + j;
    u64 wax[2], wbx[2], wah[8], wbh[8];
    u64 wia[8], wib[8], wha[8], whb[8];
#pragma unroll
    for (int k = 0; k < 2; k++) {
        wax[k] = pack2(0.5f * __ldg(&w_ih0[iR * 2 + k]), 0.5f * __ldg(&w_ih0[fR * 2 + k]));
        wbx[k] = pack2(       __ldg(&w_ih0[gR * 2 + k]), 0.5f * __ldg(&w_ih0[oR * 2 + k]));
    }
#pragma unroll
    for (int k = 0; k < 8; k++) {
        wah[k] = pack2(0.5f * __ldg(&w_hh0[iR * 8 + k]), 0.5f * __ldg(&w_hh0[fR * 8 + k]));
        wbh[k] = pack2(       __ldg(&w_hh0[gR * 8 + k]), 0.5f * __ldg(&w_hh0[oR * 8 + k]));
        wia[k] = pack2(0.5f * __ldg(&w_ih1[iR * 8 + k]), 0.5f * __ldg(&w_ih1[fR * 8 + k]));
        wib[k] = pack2(       __ldg(&w_ih1[gR * 8 + k]), 0.5f * __ldg(&w_ih1[oR * 8 + k]));
        wha[k] = pack2(0.5f * __ldg(&w_hh1[iR * 8 + k]), 0.5f * __ldg(&w_hh1[fR * 8 + k]));
        whb[k] = pack2(       __ldg(&w_hh1[gR * 8 + k]), 0.5f * __ldg(&w_hh1[oR * 8 + k]));
    }
    u64 bA0 = pack2(0.5f * (__ldg(&b_ih0[iR]) + __ldg(&b_hh0[iR])),
                    0.5f * (__ldg(&b_ih0[fR]) + __ldg(&b_hh0[fR])));
    u64 bB0 = pack2(       (__ldg(&b_ih0[gR]) + __ldg(&b_hh0[gR])),
                    0.5f * (__ldg(&b_ih0[oR]) + __ldg(&b_hh0[oR])));
    u64 bA1 = pack2(0.5f * (__ldg(&b_ih1[iR]) + __ldg(&b_hh1[iR])),
                    0.5f * (__ldg(&b_ih1[fR]) + __ldg(&b_hh1[fR])));
    u64 bB1 = pack2(       (__ldg(&b_ih1[gR]) + __ldg(&b_hh1[gR])),
                    0.5f * (__ldg(&b_ih1[oR]) + __ldg(&b_hh1[oR])));

    // Cell state packed across element pairs: c*p[pp] = (c[2pp], c[2pp+1]).
    u64 c0p[2] = { 0ull, 0ull }, c1p[2] = { 0ull, 0ull };

    int strideT = B >> 1;
    const ulonglong2* xp = (const ulonglong2*)x + 2 * q;
    ulonglong2 xa = __ldg(xp);
    ulonglong2 xb = __ldg(xp + 1);

    // ================= Prologue: h0(0) = L0(x(0), 0); h1d[0] = 0 =================
    {
#pragma unroll
        for (int p = 0; p < 4; p++)
            *(u64*)&h1d[0][p][ql][j][0] = 0ull;
        u64 xe[4] = { xa.x, xa.y, xb.x, xb.y };
#pragma unroll
        for (int pp = 0; pp < 2; pp++) {
            u64 zA[2], zB[2];
#pragma unroll
            for (int e = 0; e < 2; e++) {
                float2 xu = unpack2(xe[2 * pp + e]);
                u64 xd0 = pack2(xu.x, xu.x), xd1 = pack2(xu.y, xu.y);
                u64 a = ffma2(wax[0], xd0, bA0); a = ffma2(wax[1], xd1, a);
                u64 b = ffma2(wbx[0], xd0, bB0); b = ffma2(wbx[1], xd1, b);
                zA[e] = a; zB[e] = b;
            }
            float h_0, h_1;
            act_pair(zA[0], zA[1], zB[0], zB[1], c0p[pp], h_0, h_1);
            *(u64*)&h0d[0][2 * pp    ][ql][j][0] = pack2(h_0, h_0);
            *(u64*)&h0d[0][2 * pp + 1][ql][j][0] = pack2(h_1, h_1);
        }
        __syncwarp();
        if (T > 1) { xp += strideT; xa = __ldg(xp); xb = __ldg(xp + 1); }
    }

    // ============ Main loop: i = 1..T-1 computes h0(i) & h1(i-1) ============
#pragma unroll 1
    for (int i = 1; i < T; i++) {
        const ulonglong2* xn = xp + ((i + 1 < T) ? strideT : 0);
        ulonglong2 na = __ldg(xn);
        ulonglong2 nb = __ldg(xn + 1);
        int s = i & 1, s1 = s ^ 1;
        u64 xe[4] = { xa.x, xa.y, xb.x, xb.y };

#pragma unroll
        for (int pp = 0; pp < 2; pp++) {
            u64 zA0[2], zB0[2], zA1[2], zB1[2];
#pragma unroll
            for (int e = 0; e < 2; e++) {
                int p = 2 * pp + e;
                const ulonglong2* r0 = (const ulonglong2*)&h0d[s1][p][ql][0][0];
                ulonglong2 v0 = r0[0], v1 = r0[1], v2 = r0[2], v3 = r0[3];
                u64 hd0[8] = { v0.x, v0.y, v1.x, v1.y, v2.x, v2.y, v3.x, v3.y };
                const ulonglong2* r1 = (const ulonglong2*)&h1d[s1][p][ql][0][0];
                ulonglong2 w0 = r1[0], w1 = r1[1], w2 = r1[2], w3 = r1[3];
                u64 hd1[8] = { w0.x, w0.y, w1.x, w1.y, w2.x, w2.y, w3.x, w3.y };

                float2 xu = unpack2(xe[p]);
                u64 xd0 = pack2(xu.x, xu.x), xd1 = pack2(xu.y, xu.y);

                u64 a0 = ffma2(wax[0], xd0, bA0); a0 = ffma2(wax[1], xd1, a0);
                u64 b0 = ffma2(wbx[0], xd0, bB0); b0 = ffma2(wbx[1], xd1, b0);
                u64 a1 = bA1, b1 = bB1;
#pragma unroll
                for (int k = 0; k < 8; k++) {
                    a0 = ffma2(wah[k], hd0[k], a0);
                    b0 = ffma2(wbh[k], hd0[k], b0);
                    a1 = ffma2(wia[k], hd0[k], a1);
                    b1 = ffma2(wib[k], hd0[k], b1);
                }
#pragma unroll
                for (int k = 0; k < 8; k++) {
                    a1 = ffma2(wha[k], hd1[k], a1);
                    b1 = ffma2(whb[k], hd1[k], b1);
                }
                zA0[e] = a0; zB0[e] = b0; zA1[e] = a1; zB1[e] = b1;
            }
            float p0h0, p1h0, p0h1, p1h1;
            act_pair(zA0[0], zA0[1], zB0[0], zB0[1], c0p[pp], p0h0, p1h0);
            act_pair(zA1[0], zA1[1], zB1[0], zB1[1], c1p[pp], p0h1, p1h1);
            *(u64*)&h0d[s][2 * pp    ][ql][j][0] = pack2(p0h0, p0h0);
            *(u64*)&h0d[s][2 * pp + 1][ql][j][0] = pack2(p1h0, p1h0);
            *(u64*)&h1d[s][2 * pp    ][ql][j][0] = pack2(p0h1, p0h1);
            *(u64*)&h1d[s][2 * pp + 1][ql][j][0] = pack2(p1h1, p1h1);
        }
        __syncwarp();
        xa = na; xb = nb; xp = xn;
    }

    // ============ Epilogue: h1(T-1) = L1(h0(T-1), h1(T-2)) + FC ============
    {
        int sl = (T - 1) & 1;
        float h1f[4];
#pragma unroll
        for (int pp = 0; pp < 2; pp++) {
            u64 zA1[2], zB1[2];
#pragma unroll
            for (int e = 0; e < 2; e++) {
                int p = 2 * pp + e;
                const ulonglong2* r0 = (const ulonglong2*)&h0d[sl][p][ql][0][0];
                ulonglong2 v0 = r0[0], v1 = r0[1], v2 = r0[2], v3 = r0[3];
                u64 hd0[8] = { v0.x, v0.y, v1.x, v1.y, v2.x, v2.y, v3.x, v3.y };
                const ulonglong2* r1 = (const ulonglong2*)&h1d[sl][p][ql][0][0];
                ulonglong2 w0 = r1[0], w1 = r1[1], w2 = r1[2], w3 = r1[3];
                u64 hd1[8] = { w0.x, w0.y, w1.x, w1.y, w2.x, w2.y, w3.x, w3.y };

                u64 a1 = bA1, b1 = bB1;
#pragma unroll
                for (int k = 0; k < 8; k++) {
                    a1 = ffma2(wia[k], hd0[k], a1);
                    b1 = ffma2(wib[k], hd0[k], b1);
                }
#pragma unroll
                for (int k = 0; k < 8; k++) {
                    a1 = ffma2(wha[k], hd1[k], a1);
                    b1 = ffma2(whb[k], hd1[k], b1);
                }
                zA1[e] = a1; zB1[e] = b1;
            }
            float ha, hb;
            act_pair(zA1[0], zA1[1], zB1[0], zB1[1], c1p[pp], ha, hb);
            h1f[2 * pp] = ha; h1f[2 * pp + 1] = hb;
        }

        // FC: out[b] = sum_j fc_w[j]*h1[j] + fc_b via width-8 shfl reduction.
        float fwj = __ldg(&fc_w[j]);
        float fb  = __ldg(&fc_b[0]);
        float4 o;
        float* op = &o.x;
#pragma unroll
        for (int p = 0; p < 4; p++) {
            float v = fwj * h1f[p];
#pragma unroll
            for (int d = 4; d >= 1; d >>= 1)
                v += __shfl_down_sync(0xffffffffu, v, d, 8);
            op[p] = v + fb;
        }
        if (valid && j == 0)
            *(float4*)&out[4 * q] = o;
    }
}

extern "C" void kernel_launch(void* const* d_in, const int* in_sizes, int n_in,
                              void* d_out, int out_size)
{
    const float* x      = (const float*)d_in[0];
    const float* w_ih0  = (const float*)d_in[1];
    const float* w_hh0  = (const float*)d_in[2];
    const float* b_ih0  = (const float*)d_in[3];
    const float* b_hh0  = (const float*)d_in[4];
    const float* w_ih1  = (const float*)d_in[5];
    const float* w_hh1  = (const float*)d_in[6];
    const float* b_ih1  = (const float*)d_in[7];
    const float* b_hh1  = (const float*)d_in[8];
    const float* fc_w   = (const float*)d_in[9];
    const float* fc_b   = (const float*)d_in[10];
    float* out = (float*)d_out;

    int B = out_size;                 // [B, 1]
    int T = in_sizes[0] / (2 * B);    // x: [T, B, 2]

    int blocks = (B + 15) / 16;       // 16 elements per warp-block
    lstm2_fc_kernel<<<blocks, 32>>>(x, w_ih0, w_hh0, b_ih0, b_hh0,
                                    w_ih1, w_hh1, b_ih1, b_hh1,
                                    fc_w, fc_b, out, T, B);
}